// round 16
// baseline (speedup 1.0000x reference)
#include <cuda_runtime.h>
#include <cuda_fp16.h>
#include <cstdint>

// ---------------------------------------------------------------------------
// MemoryRetriever forward, sm_103a (compute_103 generic PTX only).
// Big GEMMs + attention on fp16 mma.sync (HMMA), fp32 accumulate.
// R16: GEMM CTA tile 256x128, 8 warps x (64x64) tiles — halves A-fragment
// redundancy so the smem crossbar is no longer the binder (keeps 4 warps/SMSP).
// ---------------------------------------------------------------------------

#define BS_TOK   16384
#define HID      1024
#define MEMD     256
#define NHEAD    4
#define HDIM     64
#define NMEM     4096
#define TOPK     512
#define CATD     1280
#define H2D      2048

// ------------------------------- scratch -----------------------------------
__device__ float  g_MEM [TOPK * MEMD];
__device__ float  g_BQ  [MEMD];
__device__ int    g_idx [TOPK];
__device__ float  g_B3  [3072];                  // [gate_b ; int_b1]

__device__ __half g_KVh [TOPK * 512];            // [512,512]: K cols 0-255, V 256-511
__device__ __half g_Qh  [(size_t)BS_TOK * MEMD];
__device__ __half g_CAT [(size_t)BS_TOK * CATD];
__device__ __half g_CTX [(size_t)BS_TOK * MEMD];
__device__ __half g_GATEh[(size_t)BS_TOK * HID];
__device__ __half g_Hpre [(size_t)BS_TOK * H2D];
__device__ __half g_Hh  [(size_t)BS_TOK * H2D];
__device__ __half g_INTh[(size_t)BS_TOK * HID];
__device__ __half g_WQ  [MEMD * HID];
__device__ __half g_GW1 [3072 * CATD];           // [gate_w ; int_w1] combined
__device__ __half g_W2  [HID * H2D];
__device__ __half g_OW  [MEMD * MEMD];

// ----------------------------- ptx helpers ---------------------------------
#define FMA2(c, a, b)    asm("fma.rn.f32x2 %0, %1, %2, %0;" : "+l"(c) : "l"(a), "l"(b))
#define UNPACK2(x, y, d) asm("mov.b64 {%0, %1}, %2;" : "=f"(x), "=f"(y) : "l"(d))

__device__ __forceinline__ uint32_t smem_u32(const void* p) {
    uint32_t a;
    asm("{ .reg .u64 t; cvta.to.shared.u64 t, %1; cvt.u32.u64 %0, t; }"
        : "=r"(a) : "l"(p));
    return a;
}

#define CP_ASYNC16(dst, src) \
    asm volatile("cp.async.cg.shared.global [%0], [%1], 16;" \
                 :: "r"(dst), "l"(src) : "memory")
#define CP_COMMIT()  asm volatile("cp.async.commit_group;" ::: "memory")
#define CP_WAIT0()   asm volatile("cp.async.wait_group 0;" ::: "memory")
#define CP_WAIT1()   asm volatile("cp.async.wait_group 1;" ::: "memory")

#define LDSM_X4(r0, r1, r2, r3, a) \
    asm volatile("ldmatrix.sync.aligned.m8n8.x4.shared.b16 {%0,%1,%2,%3}, [%4];" \
                 : "=r"(r0), "=r"(r1), "=r"(r2), "=r"(r3) : "r"(a))

#define LDSM_X4T(r0, r1, r2, r3, a) \
    asm volatile("ldmatrix.sync.aligned.m8n8.x4.trans.shared.b16 {%0,%1,%2,%3}, [%4];" \
                 : "=r"(r0), "=r"(r1), "=r"(r2), "=r"(r3) : "r"(a))

#define MMA16816(d, a, b0, b1) \
    asm volatile("mma.sync.aligned.m16n8k16.row.col.f32.f16.f16.f32 " \
                 "{%0,%1,%2,%3}, {%4,%5,%6,%7}, {%8,%9}, {%0,%1,%2,%3};" \
                 : "+f"((d)[0]), "+f"((d)[1]), "+f"((d)[2]), "+f"((d)[3]) \
                 : "r"((a)[0]), "r"((a)[1]), "r"((a)[2]), "r"((a)[3]), \
                   "r"(b0), "r"(b1))

// ---------------------------------------------------------------------------
// fp16 HMMA GEMM:  C[M,N] = A[M,K]@B[N,K]^T + bias  (fp32 accumulate)
// act: 2 fp16 out, 3 fused: col<1024 sigmoid->g_GATEh, col>=1024 ->g_Hpre.
// CTA 256x128, BK=32, 8 warps (4x2), warp tile 64x64, 3-stage cp.async,
// 80B rows. M multiple of 256, N multiple of 128.
// ---------------------------------------------------------------------------
#define TILEA_B  20480                 // 256 rows * 80 bytes
#define TILEB_B  10240                 // 128 rows * 80 bytes
#define STAGE_B  (TILEA_B + TILEB_B)   // 30720
#define GSMEM    (3 * STAGE_B)         // 92160

__global__ void __launch_bounds__(256, 2)
mr_mma_gemm(const __half* __restrict__ A, int lda,
            const __half* __restrict__ B, int ldb,
            const float* __restrict__ bias,
            __half* __restrict__ Ch,
            int ldc, int K, int act)
{
    extern __shared__ char smem[];
    const uint32_t sb = smem_u32(smem);
    const int tid  = threadIdx.x;
    const int lane = tid & 31;
    const int w    = tid >> 5;
    const int row0 = blockIdx.y * 256;
    const int col0 = blockIdx.x * 128;

    const int mbase = (w >> 1) * 64;     // 4 M-groups
    const int nbase = (w & 1) * 64;      // 2 N-groups

    const int grp = lane >> 3;
    const int r8  = lane & 7;
    const uint32_t a_row = (uint32_t)(mbase + (grp & 1) * 8 + r8) * 80 + (grp >> 1) * 16;
    const uint32_t b_row = (uint32_t)(nbase + (grp >> 1) * 8 + r8) * 80 + (grp & 1) * 16;

    const __half* srcA = A + (size_t)row0 * lda;
    const __half* srcB = B + (size_t)col0 * ldb;

    float acc[4][8][4];
    #pragma unroll
    for (int i = 0; i < 4; i++)
        #pragma unroll
        for (int j = 0; j < 8; j++)
            #pragma unroll
            for (int q = 0; q < 4; q++) acc[i][j][q] = 0.f;

    const int NC = K >> 5;

    auto issue_chunk = [&](int c) {
        const int kk = c << 5;
        const uint32_t st = sb + (uint32_t)(c % 3) * STAGE_B;
        // A: 1024 16B loads (4/thread)
        #pragma unroll
        for (int i = 0; i < 4; i++) {
            int id = tid + i * 256;
            int r = id >> 2, q = id & 3;
            CP_ASYNC16(st + r * 80 + q * 16, srcA + (size_t)r * lda + kk + q * 8);
        }
        // B: 512 16B loads (2/thread)
        #pragma unroll
        for (int i = 0; i < 2; i++) {
            int id = tid + i * 256;
            int r = id >> 2, q = id & 3;
            CP_ASYNC16(st + TILEA_B + r * 80 + q * 16, srcB + (size_t)r * ldb + kk + q * 8);
        }
        CP_COMMIT();
    };

    issue_chunk(0);
    if (NC > 1) issue_chunk(1);

    for (int c = 0; c < NC; c++) {
        if (c + 1 < NC) CP_WAIT1(); else CP_WAIT0();
        __syncthreads();
        if (c + 2 < NC) issue_chunk(c + 2);

        const uint32_t st = sb + (uint32_t)(c % 3) * STAGE_B;
        const uint32_t sA = st, sB2 = st + TILEA_B;

        #pragma unroll
        for (int ks = 0; ks < 2; ks++) {
            const uint32_t koff = (uint32_t)ks * 32;
            uint32_t a[4][4], b[4][4];
            #pragma unroll
            for (int mi = 0; mi < 4; mi++)
                LDSM_X4(a[mi][0], a[mi][1], a[mi][2], a[mi][3],
                        sA + a_row + (uint32_t)mi * (16 * 80) + koff);
            #pragma unroll
            for (int p = 0; p < 4; p++)
                LDSM_X4(b[p][0], b[p][1], b[p][2], b[p][3],
                        sB2 + b_row + (uint32_t)p * (16 * 80) + koff);
            #pragma unroll
            for (int mi = 0; mi < 4; mi++)
                #pragma unroll
                for (int nt = 0; nt < 8; nt++) {
                    const int p = nt >> 1, q = (nt & 1) * 2;
                    MMA16816(acc[mi][nt], a[mi], b[p][q], b[p][q + 1]);
                }
        }
    }

    // ---------------- epilogue ----------------
    const int l4 = lane >> 2;
    const int l2 = (lane & 3) * 2;
    #pragma unroll
    for (int mi = 0; mi < 4; mi++) {
        #pragma unroll
        for (int nt = 0; nt < 8; nt++) {
            const int gm = row0 + mbase + mi * 16 + l4;
            const int gn = col0 + nbase + nt * 8 + l2;
            float2 bb = *(const float2*)(bias + gn);
            #pragma unroll
            for (int half_ = 0; half_ < 2; half_++) {
                const int rr = gm + half_ * 8;
                float x = acc[mi][nt][2 * half_]     + bb.x;
                float y = acc[mi][nt][2 * half_ + 1] + bb.y;
                if (act == 3) {
                    if (gn < 1024) {   // uniform per CTA (col0 128-aligned)
                        x = 1.f / (1.f + expf(-x));
                        y = 1.f / (1.f + expf(-y));
                        *(__half2*)(g_GATEh + (size_t)rr * HID + gn) =
                            __floats2half2_rn(x, y);
                    } else {
                        *(__half2*)(g_Hpre + (size_t)rr * H2D + gn - 1024) =
                            __floats2half2_rn(x, y);
                    }
                } else {
                    *(__half2*)(Ch + (size_t)rr * ldc + gn) = __floats2half2_rn(x, y);
                }
            }
        }
    }
}

// ---------------------------------------------------------------------------
// Flash-style fp16 attention (unchanged, proven).
// ---------------------------------------------------------------------------
#define AT_ROW   144
#define AT_TILE  (128 * AT_ROW)
#define AT_SMEM  (5 * AT_TILE)

__global__ void __launch_bounds__(256)
mr_fattn_kernel()
{
    extern __shared__ char smem[];
    const uint32_t sQ = smem_u32(smem);
    const int tid  = threadIdx.x;
    const int lane = tid & 31;
    const int w    = tid >> 5;
    const int h    = blockIdx.y;
    const int tok0 = blockIdx.x * 128;

    const uint32_t sK[2] = { sQ + AT_TILE,     sQ + 3 * AT_TILE };
    const uint32_t sV[2] = { sQ + 2 * AT_TILE, sQ + 4 * AT_TILE };

    const int srow = tid >> 1;
    const int sq2  = (tid & 1) * 4;

    auto load_q = [&]() {
        const __half* src = g_Qh + (size_t)(tok0 + srow) * MEMD + h * HDIM + sq2 * 8;
        uint32_t dst = sQ + srow * AT_ROW + sq2 * 16;
        #pragma unroll
        for (int u = 0; u < 4; u++) CP_ASYNC16(dst + u * 16, src + u * 8);
    };
    auto load_kv = [&](int c) {
        const int b = c & 1;
        const __half* ks = g_KVh + (size_t)(c * 128 + srow) * 512 + h * HDIM + sq2 * 8;
        const __half* vs = ks + 256;
        uint32_t kd = sK[b] + srow * AT_ROW + sq2 * 16;
        uint32_t vd = sV[b] + srow * AT_ROW + sq2 * 16;
        #pragma unroll
        for (int u = 0; u < 4; u++) { CP_ASYNC16(kd + u * 16, ks + u * 8); CP_ASYNC16(vd + u * 16, vs + u * 8); }
    };

    load_q(); load_kv(0); CP_COMMIT();
    load_kv(1); CP_COMMIT();
    CP_WAIT1();
    __syncthreads();

    const int grp = lane >> 3;
    const int r8  = lane & 7;
    const int wbase = w * 16;
    const uint32_t a_addr = (uint32_t)(wbase + (grp & 1) * 8 + r8) * AT_ROW + (grp >> 1) * 16;
    const uint32_t b_addr = (uint32_t)((grp >> 1) * 8 + r8) * AT_ROW + (grp & 1) * 16;
    const uint32_t v_addr = (uint32_t)(r8 + 8 * (grp & 1)) * AT_ROW + (lane >> 4) * 16;

    uint32_t qf[4][4];
    #pragma unroll
    for (int kk = 0; kk < 4; kk++)
        LDSM_X4(qf[kk][0], qf[kk][1], qf[kk][2], qf[kk][3],
                sQ + a_addr + kk * 32);

    float ctx[8][4];
    #pragma unroll
    for (int i = 0; i < 8; i++)
        #pragma unroll
        for (int q = 0; q < 4; q++) ctx[i][q] = 0.f;
    float lrow = 0.f, lrow8 = 0.f;

    for (int c = 0; c < 4; c++) {
        const int b = c & 1;

        float sacc[16][4];
        #pragma unroll
        for (int i = 0; i < 16; i++)
            #pragma unroll
            for (int q = 0; q < 4; q++) sacc[i][q] = 0.f;

        #pragma unroll
        for (int nt2 = 0; nt2 < 8; nt2++) {
            #pragma unroll
            for (int kk = 0; kk < 4; kk++) {
                uint32_t kb[4];
                LDSM_X4(kb[0], kb[1], kb[2], kb[3],
                        sK[b] + b_addr + (uint32_t)nt2 * (16 * AT_ROW) + kk * 32);
                MMA16816(sacc[2 * nt2],     qf[kk], kb[0], kb[1]);
                MMA16816(sacc[2 * nt2 + 1], qf[kk], kb[2], kb[3]);
            }
        }

        uint32_t pf[8][4];
        #pragma unroll
        for (int kf = 0; kf < 8; kf++) {
            float e00 = __expf(sacc[2 * kf][0]);
            float e01 = __expf(sacc[2 * kf][1]);
            float e02 = __expf(sacc[2 * kf][2]);
            float e03 = __expf(sacc[2 * kf][3]);
            float e10 = __expf(sacc[2 * kf + 1][0]);
            float e11 = __expf(sacc[2 * kf + 1][1]);
            float e12 = __expf(sacc[2 * kf + 1][2]);
            float e13 = __expf(sacc[2 * kf + 1][3]);
            lrow  += e00 + e01 + e10 + e11;
            lrow8 += e02 + e03 + e12 + e13;
            __half2 h0 = __floats2half2_rn(e00, e01);
            __half2 h1 = __floats2half2_rn(e02, e03);
            __half2 h2 = __floats2half2_rn(e10, e11);
            __half2 h3 = __floats2half2_rn(e12, e13);
            pf[kf][0] = *(uint32_t*)&h0;
            pf[kf][1] = *(uint32_t*)&h1;
            pf[kf][2] = *(uint32_t*)&h2;
            pf[kf][3] = *(uint32_t*)&h3;
        }

        #pragma unroll
        for (int dt2 = 0; dt2 < 4; dt2++) {
            #pragma unroll
            for (int kf = 0; kf < 8; kf++) {
                uint32_t vb[4];
                LDSM_X4T(vb[0], vb[1], vb[2], vb[3],
                         sV[b] + v_addr + (uint32_t)kf * (16 * AT_ROW) + dt2 * 32);
                MMA16816(ctx[2 * dt2],     pf[kf], vb[0], vb[1]);
                MMA16816(ctx[2 * dt2 + 1], pf[kf], vb[2], vb[3]);
            }
        }

        __syncthreads();
        if (c + 2 < 4) { load_kv(c + 2); CP_COMMIT(); }
        if (c + 1 < 4) {
            if (c + 2 < 4) CP_WAIT1(); else CP_WAIT0();
            __syncthreads();
        }
    }

    lrow  += __shfl_xor_sync(0xffffffffu, lrow, 1);
    lrow  += __shfl_xor_sync(0xffffffffu, lrow, 2);
    lrow8 += __shfl_xor_sync(0xffffffffu, lrow8, 1);
    lrow8 += __shfl_xor_sync(0xffffffffu, lrow8, 2);
    const float inv  = 1.f / lrow;
    const float inv8 = 1.f / lrow8;

    const int rowA = tok0 + wbase + (lane >> 2);
    const int colb = h * HDIM + 2 * (lane & 3);
    #pragma unroll
    for (int dt = 0; dt < 8; dt++) {
        int gn = colb + dt * 8;
        *(__half2*)(g_CTX + (size_t)rowA * MEMD + gn) =
            __floats2half2_rn(ctx[dt][0] * inv, ctx[dt][1] * inv);
        *(__half2*)(g_CTX + (size_t)(rowA + 8) * MEMD + gn) =
            __floats2half2_rn(ctx[dt][2] * inv8, ctx[dt][3] * inv8);
    }
}

// ---------------------------------------------------------------------------
// top-k by rank counting (exact set == lax.top_k)
// ---------------------------------------------------------------------------
__global__ void mr_topk_kernel(const float* __restrict__ scores) {
    __shared__ float s[NMEM];
    for (int i = threadIdx.x; i < NMEM; i += 512) s[i] = scores[i];
    __syncthreads();
    int i = blockIdx.x * 512 + threadIdx.x;
    float si = s[i];
    int cnt = 0;
    #pragma unroll 8
    for (int j = 0; j < NMEM; j++) {
        float sj = s[j];
        cnt += (sj > si) || (sj == si && j < i);
    }
    if (cnt < TOPK) g_idx[cnt] = i;
}

// Wq_comb = (wq @ qp_w)/8 -> fp16 ;  bq_comb = (wq@qp_b + bq)/8
__global__ void mr_wqcomb_kernel(const float* __restrict__ in_proj_w,
                                 const float* __restrict__ qp_w,
                                 const float* __restrict__ qp_b,
                                 const float* __restrict__ in_proj_b) {
    int m = blockIdx.x;
    __shared__ float wrow[MEMD];
    for (int j = threadIdx.x; j < MEMD; j += 256)
        wrow[j] = in_proj_w[(size_t)m * MEMD + j];
    __syncthreads();
    #pragma unroll
    for (int cc = 0; cc < HID / 256; cc++) {
        int hcol = threadIdx.x + 256 * cc;
        float acc = 0.f;
        #pragma unroll 8
        for (int j = 0; j < MEMD; j++)
            acc += wrow[j] * qp_w[(size_t)j * HID + hcol];
        g_WQ[(size_t)m * HID + hcol] = __float2half_rn(0.125f * acc);
    }
    if (threadIdx.x == 0) {
        float acc = in_proj_b[m];
        for (int j = 0; j < MEMD; j++) acc += wrow[j] * qp_b[j];
        g_BQ[m] = 0.125f * acc;
    }
}

__device__ __forceinline__ void block_reduce2(float& a, float& b) {
    #pragma unroll
    for (int o = 16; o > 0; o >>= 1) {
        a += __shfl_xor_sync(0xffffffffu, a, o);
        b += __shfl_xor_sync(0xffffffffu, b, o);
    }
    __shared__ float sa[8], sb2[8];
    int w = threadIdx.x >> 5;
    if ((threadIdx.x & 31) == 0) { sa[w] = a; sb2[w] = b; }
    __syncthreads();
    a = 0.f; b = 0.f;
    #pragma unroll
    for (int i = 0; i < 8; i++) { a += sa[i]; b += sb2[i]; }
}

__global__ void mr_gather_ln_kernel(const float* __restrict__ mk,
                                    const float* __restrict__ g,
                                    const float* __restrict__ b) {
    int r = blockIdx.x;
    int t = threadIdx.x;
    float v = mk[(size_t)g_idx[r] * MEMD + t];
    float s = v, ss = v * v;
    block_reduce2(s, ss);
    float mu  = s * (1.f / MEMD);
    float var = ss * (1.f / MEMD) - mu * mu;
    g_MEM[(size_t)r * MEMD + t] = (v - mu) * rsqrtf(var + 1e-5f) * g[t] + b[t];
}

// fp32 -> fp16, vectorized
__global__ void mr_cvt_kernel(const float* __restrict__ s,
                              __half* __restrict__ d, int n4) {
    int i = blockIdx.x * 256 + threadIdx.x;
    if (i >= n4) return;
    float4 v = ((const float4*)s)[i];
    ((__half2*)d)[2 * i]     = __floats2half2_rn(v.x, v.y);
    ((__half2*)d)[2 * i + 1] = __floats2half2_rn(v.z, v.w);
}

// X -> CAT left 1024 columns (fp16)
__global__ void mr_copyx_cvt_kernel(const float* __restrict__ X) {
    size_t i4  = (size_t)blockIdx.x * 256 + threadIdx.x;
    size_t row = i4 >> 8;
    size_t c4  = i4 & 255;
    float4 v = ((const float4*)X)[i4];
    size_t o = row * CATD + c4 * 4;
    *(__half2*)(g_CAT + o)     = __floats2half2_rn(v.x, v.y);
    *(__half2*)(g_CAT + o + 2) = __floats2half2_rn(v.z, v.w);
}

// ---------------------------------------------------------------------------
// FFMA2 SGEMM (K/V projection): C(half) = A@B^T + bias
// ---------------------------------------------------------------------------
__global__ void __launch_bounds__(256) mr_sgemm_kernel(
    const float* __restrict__ A, const float* __restrict__ B,
    const float* __restrict__ bias, __half* __restrict__ C,
    int K, int ldc)
{
    __shared__ float2 As[8][128];
    __shared__ float  Bs[8][128];

    const int tid  = threadIdx.x;
    const int row0 = blockIdx.y * 128;
    const int col0 = blockIdx.x * 128;
    const int lr   = tid >> 1;
    const int lh   = tid & 1;
    const float* Ag = A + (size_t)(row0 + lr) * K + lh * 4;
    const float* Bg = B + (size_t)(col0 + lr) * K + lh * 4;
    const int tx = tid & 15;
    const int ty = tid >> 4;

    unsigned long long acc[8][4];
    #pragma unroll
    for (int i = 0; i < 8; i++)
        #pragma unroll
        for (int j = 0; j < 4; j++) acc[i][j] = 0ULL;

    for (int kt = 0; kt < K; kt += 8) {
        float4 av = *(const float4*)(Ag + kt);
        float4 bv = *(const float4*)(Bg + kt);
        __syncthreads();
        As[lh * 4 + 0][lr] = make_float2(av.x, av.x);
        As[lh * 4 + 1][lr] = make_float2(av.y, av.y);
        As[lh * 4 + 2][lr] = make_float2(av.z, av.z);
        As[lh * 4 + 3][lr] = make_float2(av.w, av.w);
        Bs[lh * 4 + 0][lr] = bv.x;
        Bs[lh * 4 + 1][lr] = bv.y;
        Bs[lh * 4 + 2][lr] = bv.z;
        Bs[lh * 4 + 3][lr] = bv.w;
        __syncthreads();
        #pragma unroll
        for (int kk = 0; kk < 8; kk++) {
            unsigned long long a2[8], b2[4];
            const unsigned long long* ap = (const unsigned long long*)&As[kk][ty * 8];
            #pragma unroll
            for (int i = 0; i < 8; i++) a2[i] = ap[i];
            const unsigned long long* bp = (const unsigned long long*)&Bs[kk][tx * 8];
            #pragma unroll
            for (int j = 0; j < 4; j++) b2[j] = bp[j];
            #pragma unroll
            for (int i = 0; i < 8; i++)
                #pragma unroll
                for (int j = 0; j < 4; j++)
                    FMA2(acc[i][j], a2[i], b2[j]);
        }
    }

    #pragma unroll
    for (int i = 0; i < 8; i++) {
        __half* crow = C + (size_t)(row0 + ty * 8 + i) * ldc + col0 + tx * 8;
        #pragma unroll
        for (int j = 0; j < 4; j++) {
            float x, y;
            UNPACK2(x, y, acc[i][j]);
            float2 bb = *(const float2*)(bias + col0 + tx * 8 + 2 * j);
            *(__half2*)(crow + 2 * j) = __floats2half2_rn(x + bb.x, y + bb.y);
        }
    }
}

// h = gelu_exact(LN(h_pre)) -> fp16  (h_pre fp16 in, stats fp32)
__global__ void mr_ln_gelu_kernel(const float* __restrict__ g,
                                  const float* __restrict__ b) {
    const size_t row = blockIdx.x;
    const __half2* p = (const __half2*)(g_Hpre + row * H2D);
    float x[8];
    #pragma unroll
    for (int i = 0; i < 4; i++) {
        float2 v = __half22float2(p[threadIdx.x + 256 * i]);
        x[2 * i] = v.x; x[2 * i + 1] = v.y;
    }
    float s = 0.f, ss = 0.f;
    #pragma unroll
    for (int i = 0; i < 8; i++) { s += x[i]; ss += x[i] * x[i]; }
    block_reduce2(s, ss);
    float mu  = s * (1.f / H2D);
    float var = ss * (1.f / H2D) - mu * mu;
    float rs  = rsqrtf(var + 1e-5f);
    #pragma unroll
    for (int i = 0; i < 4; i++) {
        int col = (threadIdx.x + 256 * i) * 2;
        float t0 = (x[2 * i]     - mu) * rs * g[col]     + b[col];
        float t1 = (x[2 * i + 1] - mu) * rs * g[col + 1] + b[col + 1];
        float g0 = 0.5f * t0 * (1.f + erff(t0 * 0.70710678118654752f));
        float g1 = 0.5f * t1 * (1.f + erff(t1 * 0.70710678118654752f));
        *(__half2*)(g_Hh + row * H2D + col) = __floats2half2_rn(g0, g1);
    }
}

// out = LN(X + gate*integ)   (gate/integ fp16, X fp32)
__global__ void mr_final_kernel(const float* __restrict__ X,
                                const float* __restrict__ g,
                                const float* __restrict__ b,
                                float* __restrict__ out) {
    const size_t row = blockIdx.x;
    const float*  xp = X + row * HID;
    const __half2* gp = (const __half2*)(g_GATEh + row * HID);
    const __half2* ip = (const __half2*)(g_INTh + row * HID);
    float v[4];
    float s = 0.f, ss = 0.f;
    #pragma unroll
    for (int i = 0; i < 2; i++) {
        int c2 = threadIdx.x + 256 * i;
        float2 gg = __half22float2(gp[c2]);
        float2 ii = __half22float2(ip[c2]);
        float2 xx = *(const float2*)(xp + 2 * c2);
        v[2 * i]     = xx.x + gg.x * ii.x;
        v[2 * i + 1] = xx.y + gg.y * ii.y;
        s += v[2 * i] + v[2 * i + 1];
        ss += v[2 * i] * v[2 * i] + v[2 * i + 1] * v[2 * i + 1];
    }
    block_reduce2(s, ss);
    float mu  = s * (1.f / HID);
    float var = ss * (1.f / HID) - mu * mu;
    float rs  = rsqrtf(var + 1e-5f);
    #pragma unroll
    for (int i = 0; i < 2; i++) {
        int col = (threadIdx.x + 256 * i) * 2;
        out[row * HID + col]     = (v[2 * i]     - mu) * rs * g[col]     + b[col];
        out[row * HID + col + 1] = (v[2 * i + 1] - mu) * rs * g[col + 1] + b[col + 1];
    }
}

// ---------------------------------------------------------------------------
extern "C" void kernel_launch(void* const* d_in, const int* in_sizes, int n_in,
                              void* d_out, int out_size) {
    const float* X         = (const float*)d_in[0];
    const float* mem_keys  = (const float*)d_in[1];
    const float* sel       = (const float*)d_in[2];
    const float* qp_w      = (const float*)d_in[3];
    const float* qp_b      = (const float*)d_in[4];
    const float* in_proj_w = (const float*)d_in[5];
    const float* in_proj_b = (const float*)d_in[6];
    const float* out_w     = (const float*)d_in[7];
    const float* out_b     = (const float*)d_in[8];
    const float* gate_w    = (const float*)d_in[9];
    const float* gate_b    = (const float*)d_in[10];
    const float* int_w1    = (const float*)d_in[11];
    const float* int_b1    = (const float*)d_in[12];
    const float* int_ln_g  = (const float*)d_in[13];
    const float* int_ln_b  = (const float*)d_in[14];
    const float* int_w2    = (const float*)d_in[15];
    const float* int_b2    = (const float*)d_in[16];
    const float* ln1_g     = (const float*)d_in[17];
    const float* ln1_b     = (const float*)d_in[18];
    const float* ln2_g     = (const float*)d_in[19];
    const float* ln2_b     = (const float*)d_in[20];
    float* out = (float*)d_out;

    static int smem_set = 0;
    if (!smem_set) {
        cudaFuncSetAttribute(mr_mma_gemm,
                             cudaFuncAttributeMaxDynamicSharedMemorySize, GSMEM);
        cudaFuncSetAttribute(mr_fattn_kernel,
                             cudaFuncAttributeMaxDynamicSharedMemorySize, AT_SMEM);
        smem_set = 1;
    }

    float *pMEM, *pBQ, *pB3;
    __half *pKVh, *pQh, *pCAT, *pCTX, *pINTh, *pWQ, *pGW1, *pW2, *pOW, *pHh;
    cudaGetSymbolAddress((void**)&pMEM, g_MEM);
    cudaGetSymbolAddress((void**)&pBQ,  g_BQ);
    cudaGetSymbolAddress((void**)&pB3,  g_B3);
    cudaGetSymbolAddress((void**)&pKVh, g_KVh);
    cudaGetSymbolAddress((void**)&pQh,  g_Qh);
    cudaGetSymbolAddress((void**)&pCAT, g_CAT);
    cudaGetSymbolAddress((void**)&pCTX, g_CTX);
    cudaGetSymbolAddress((void**)&pINTh, g_INTh);
    cudaGetSymbolAddress((void**)&pWQ,  g_WQ);
    cudaGetSymbolAddress((void**)&pGW1, g_GW1);
    cudaGetSymbolAddress((void**)&pW2,  g_W2);
    cudaGetSymbolAddress((void**)&pOW,  g_OW);
    cudaGetSymbolAddress((void**)&pHh,  g_Hh);

    auto mmagemm = [&](const __half* A, int lda, const __half* B, int ldb,
                       const float* bias, __half* Ch,
                       int ldc, int M, int N, int K, int act) {
        dim3 gd(N / 128, M / 256);
        mr_mma_gemm<<<gd, 256, GSMEM>>>(A, lda, B, ldb, bias, Ch, ldc, K, act);
    };

    // selection + memory prep
    mr_topk_kernel<<<8, 512>>>(sel);
    mr_wqcomb_kernel<<<256, 256>>>(in_proj_w, qp_w, qp_b, in_proj_b);
    mr_gather_ln_kernel<<<TOPK, 256>>>(mem_keys, ln1_g, ln1_b);

    // combined bias [gate_b ; int_b1]
    cudaMemcpyAsync(pB3, gate_b, HID * sizeof(float), cudaMemcpyDeviceToDevice);
    cudaMemcpyAsync(pB3 + HID, int_b1, H2D * sizeof(float), cudaMemcpyDeviceToDevice);

    // weight converts
    mr_cvt_kernel<<<(HID * CATD / 4 + 255) / 256, 256>>>(gate_w, pGW1, HID * CATD / 4);
    mr_cvt_kernel<<<(H2D * CATD / 4 + 255) / 256, 256>>>(int_w1,
        pGW1 + (size_t)HID * CATD, H2D * CATD / 4);
    mr_cvt_kernel<<<(HID * H2D / 4 + 255) / 256, 256>>>(int_w2, pW2, HID * H2D / 4);
    mr_cvt_kernel<<<(MEMD * MEMD / 4 + 255) / 256, 256>>>(out_w, pOW, MEMD * MEMD / 4);

    // K|V projection (fp16 out): KV[512,512] = MEM @ [wk;wv]^T + [bk;bv]
    {
        dim3 gd(4, 4);
        mr_sgemm_kernel<<<gd, 256>>>(pMEM, in_proj_w + MEMD * MEMD,
                                     in_proj_b + MEMD, pKVh, MEMD, 512);
    }

    // X -> CAT (left 1024 cols, fp16)
    mr_copyx_cvt_kernel<<<(size_t)BS_TOK * HID / 4 / 256, 256>>>(X);

    // q = X @ Wq_comb^T + bq  (1/8 folded)  -> fp16
    mmagemm(pCAT, CATD, pWQ, HID, pBQ, pQh, MEMD, BS_TOK, MEMD, HID, 2);

    // flash attention -> CTX (fp16)
    mr_fattn_kernel<<<dim3(BS_TOK / 128, NHEAD), 256, AT_SMEM>>>();

    // attn_out = ctx @ out_w^T + out_b  -> CAT right 256 cols (fp16)
    mmagemm(pCTX, MEMD, pOW, MEMD, out_b, pCAT + HID, CATD, BS_TOK, MEMD, MEMD, 2);

    // fused: gate = sigmoid(cat@gate_w^T+gate_b) -> fp16,
    //        h_pre = cat@int_w1^T+int_b1 -> fp16
    mmagemm(pCAT, CATD, pGW1, CATD, pB3, nullptr, 0, BS_TOK, 3072, CATD, 3);

    mr_ln_gelu_kernel<<<BS_TOK, 256>>>(int_ln_g, int_ln_b);

    // integrated = h@int_w2^T + int_b2 -> fp16
    mmagemm(pHh, H2D, pW2, H2D, int_b2, pINTh, HID, BS_TOK, HID, H2D, 2);

    // out = LN(X + gate*integrated)
    mr_final_kernel<<<BS_TOK, 256>>>(X, ln2_g, ln2_b, out);
}

// round 17
// speedup vs baseline: 1.7485x; 1.7485x over previous
#include <cuda_runtime.h>
#include <cuda_fp16.h>
#include <cstdint>

// ---------------------------------------------------------------------------
// MemoryRetriever forward, sm_103a (compute_103 generic PTX only).
// Big GEMMs + attention on fp16 mma.sync (HMMA), fp32 accumulate.
// R17: R15 config (proven best) + 4-stage cp.async pipeline in the GEMM.
// ---------------------------------------------------------------------------

#define BS_TOK   16384
#define HID      1024
#define MEMD     256
#define NHEAD    4
#define HDIM     64
#define NMEM     4096
#define TOPK     512
#define CATD     1280
#define H2D      2048

// ------------------------------- scratch -----------------------------------
__device__ float  g_MEM [TOPK * MEMD];
__device__ float  g_BQ  [MEMD];
__device__ int    g_idx [TOPK];
__device__ float  g_B3  [3072];                  // [gate_b ; int_b1]

__device__ __half g_KVh [TOPK * 512];            // [512,512]: K cols 0-255, V 256-511
__device__ __half g_Qh  [(size_t)BS_TOK * MEMD];
__device__ __half g_CAT [(size_t)BS_TOK * CATD];
__device__ __half g_CTX [(size_t)BS_TOK * MEMD];
__device__ __half g_GATEh[(size_t)BS_TOK * HID];
__device__ __half g_Hpre [(size_t)BS_TOK * H2D];
__device__ __half g_Hh  [(size_t)BS_TOK * H2D];
__device__ __half g_INTh[(size_t)BS_TOK * HID];
__device__ __half g_WQ  [MEMD * HID];
__device__ __half g_GW1 [3072 * CATD];           // [gate_w ; int_w1] combined
__device__ __half g_W2  [HID * H2D];
__device__ __half g_OW  [MEMD * MEMD];

// ----------------------------- ptx helpers ---------------------------------
#define FMA2(c, a, b)    asm("fma.rn.f32x2 %0, %1, %2, %0;" : "+l"(c) : "l"(a), "l"(b))
#define UNPACK2(x, y, d) asm("mov.b64 {%0, %1}, %2;" : "=f"(x), "=f"(y) : "l"(d))

__device__ __forceinline__ uint32_t smem_u32(const void* p) {
    uint32_t a;
    asm("{ .reg .u64 t; cvta.to.shared.u64 t, %1; cvt.u32.u64 %0, t; }"
        : "=r"(a) : "l"(p));
    return a;
}

#define CP_ASYNC16(dst, src) \
    asm volatile("cp.async.cg.shared.global [%0], [%1], 16;" \
                 :: "r"(dst), "l"(src) : "memory")
#define CP_COMMIT()  asm volatile("cp.async.commit_group;" ::: "memory")
#define CP_WAIT0()   asm volatile("cp.async.wait_group 0;" ::: "memory")
#define CP_WAIT1()   asm volatile("cp.async.wait_group 1;" ::: "memory")
#define CP_WAIT2()   asm volatile("cp.async.wait_group 2;" ::: "memory")

#define LDSM_X4(r0, r1, r2, r3, a) \
    asm volatile("ldmatrix.sync.aligned.m8n8.x4.shared.b16 {%0,%1,%2,%3}, [%4];" \
                 : "=r"(r0), "=r"(r1), "=r"(r2), "=r"(r3) : "r"(a))

#define LDSM_X4T(r0, r1, r2, r3, a) \
    asm volatile("ldmatrix.sync.aligned.m8n8.x4.trans.shared.b16 {%0,%1,%2,%3}, [%4];" \
                 : "=r"(r0), "=r"(r1), "=r"(r2), "=r"(r3) : "r"(a))

#define MMA16816(d, a, b0, b1) \
    asm volatile("mma.sync.aligned.m16n8k16.row.col.f32.f16.f16.f32 " \
                 "{%0,%1,%2,%3}, {%4,%5,%6,%7}, {%8,%9}, {%0,%1,%2,%3};" \
                 : "+f"((d)[0]), "+f"((d)[1]), "+f"((d)[2]), "+f"((d)[3]) \
                 : "r"((a)[0]), "r"((a)[1]), "r"((a)[2]), "r"((a)[3]), \
                   "r"(b0), "r"(b1))

// ---------------------------------------------------------------------------
// fp16 HMMA GEMM:  C[M,N] = A[M,K]@B[N,K]^T + bias  (fp32 accumulate)
// act: 2 fp16 out, 3 fused: col<1024 sigmoid->g_GATEh, col>=1024 ->g_Hpre.
// CTA 128x128, BK=32, 8 warps (2x4), warp 64x32, 4-stage cp.async, 80B rows.
// ---------------------------------------------------------------------------
#define TILE_B   10240
#define STAGE_B  (2 * TILE_B)
#define GSMEM    (4 * STAGE_B)          // 81920

__global__ void __launch_bounds__(256, 2)
mr_mma_gemm(const __half* __restrict__ A, int lda,
            const __half* __restrict__ B, int ldb,
            const float* __restrict__ bias,
            __half* __restrict__ Ch,
            int ldc, int K, int act)
{
    extern __shared__ char smem[];
    const uint32_t sb = smem_u32(smem);
    const int tid  = threadIdx.x;
    const int lane = tid & 31;
    const int w    = tid >> 5;
    const int row0 = blockIdx.y * 128;
    const int col0 = blockIdx.x * 128;

    const int mbase = (w >> 2) * 64;
    const int nbase = (w & 3) * 32;

    const int grp = lane >> 3;
    const int r8  = lane & 7;
    const uint32_t a_row = (uint32_t)(mbase + (grp & 1) * 8 + r8) * 80 + (grp >> 1) * 16;
    const uint32_t b_row = (uint32_t)(nbase + (grp >> 1) * 8 + r8) * 80 + (grp & 1) * 16;

    const __half* srcA = A + (size_t)row0 * lda;
    const __half* srcB = B + (size_t)col0 * ldb;

    float acc[4][4][4];
    #pragma unroll
    for (int i = 0; i < 4; i++)
        #pragma unroll
        for (int j = 0; j < 4; j++)
            #pragma unroll
            for (int q = 0; q < 4; q++) acc[i][j][q] = 0.f;

    const int NC = K >> 5;
    const int r0 = tid >> 2,         q0 = tid & 3;
    const int r1 = (tid + 256) >> 2, q1 = (tid + 256) & 3;

    auto issue_chunk = [&](int c) {
        const int kk = c << 5;
        const uint32_t st = sb + (uint32_t)(c & 3) * STAGE_B;
        CP_ASYNC16(st + r0 * 80 + q0 * 16, srcA + (size_t)r0 * lda + kk + q0 * 8);
        CP_ASYNC16(st + r1 * 80 + q1 * 16, srcA + (size_t)r1 * lda + kk + q1 * 8);
        CP_ASYNC16(st + TILE_B + r0 * 80 + q0 * 16, srcB + (size_t)r0 * ldb + kk + q0 * 8);
        CP_ASYNC16(st + TILE_B + r1 * 80 + q1 * 16, srcB + (size_t)r1 * ldb + kk + q1 * 8);
        CP_COMMIT();
    };

    issue_chunk(0);
    if (NC > 1) issue_chunk(1);
    if (NC > 2) issue_chunk(2);

    for (int c = 0; c < NC; c++) {
        if (c + 2 < NC)      CP_WAIT2();
        else if (c + 1 < NC) CP_WAIT1();
        else                 CP_WAIT0();
        __syncthreads();
        if (c + 3 < NC) issue_chunk(c + 3);

        const uint32_t st = sb + (uint32_t)(c & 3) * STAGE_B;
        const uint32_t sA = st, sB2 = st + TILE_B;

        #pragma unroll
        for (int ks = 0; ks < 2; ks++) {
            const uint32_t koff = (uint32_t)ks * 32;
            uint32_t a[4][4], b[2][4];
            #pragma unroll
            for (int mi = 0; mi < 4; mi++)
                LDSM_X4(a[mi][0], a[mi][1], a[mi][2], a[mi][3],
                        sA + a_row + (uint32_t)mi * (16 * 80) + koff);
            #pragma unroll
            for (int p = 0; p < 2; p++)
                LDSM_X4(b[p][0], b[p][1], b[p][2], b[p][3],
                        sB2 + b_row + (uint32_t)p * (16 * 80) + koff);
            #pragma unroll
            for (int mi = 0; mi < 4; mi++)
                #pragma unroll
                for (int nt = 0; nt < 4; nt++) {
                    const int p = nt >> 1, q = (nt & 1) * 2;
                    MMA16816(acc[mi][nt], a[mi], b[p][q], b[p][q + 1]);
                }
        }
    }

    // ---------------- epilogue ----------------
    const int l4 = lane >> 2;
    const int l2 = (lane & 3) * 2;
    #pragma unroll
    for (int mi = 0; mi < 4; mi++) {
        #pragma unroll
        for (int nt = 0; nt < 4; nt++) {
            const int gm = row0 + mbase + mi * 16 + l4;
            const int gn = col0 + nbase + nt * 8 + l2;
            float2 bb = *(const float2*)(bias + gn);
            #pragma unroll
            for (int half_ = 0; half_ < 2; half_++) {
                const int rr = gm + half_ * 8;
                float x = acc[mi][nt][2 * half_]     + bb.x;
                float y = acc[mi][nt][2 * half_ + 1] + bb.y;
                if (act == 3) {
                    if (gn < 1024) {   // uniform per CTA (col0 128-aligned)
                        x = 1.f / (1.f + expf(-x));
                        y = 1.f / (1.f + expf(-y));
                        *(__half2*)(g_GATEh + (size_t)rr * HID + gn) =
                            __floats2half2_rn(x, y);
                    } else {
                        *(__half2*)(g_Hpre + (size_t)rr * H2D + gn - 1024) =
                            __floats2half2_rn(x, y);
                    }
                } else {
                    *(__half2*)(Ch + (size_t)rr * ldc + gn) = __floats2half2_rn(x, y);
                }
            }
        }
    }
}

// ---------------------------------------------------------------------------
// Flash-style fp16 attention (unchanged, proven).
// ---------------------------------------------------------------------------
#define AT_ROW   144
#define AT_TILE  (128 * AT_ROW)
#define AT_SMEM  (5 * AT_TILE)

__global__ void __launch_bounds__(256)
mr_fattn_kernel()
{
    extern __shared__ char smem[];
    const uint32_t sQ = smem_u32(smem);
    const int tid  = threadIdx.x;
    const int lane = tid & 31;
    const int w    = tid >> 5;
    const int h    = blockIdx.y;
    const int tok0 = blockIdx.x * 128;

    const uint32_t sK[2] = { sQ + AT_TILE,     sQ + 3 * AT_TILE };
    const uint32_t sV[2] = { sQ + 2 * AT_TILE, sQ + 4 * AT_TILE };

    const int srow = tid >> 1;
    const int sq2  = (tid & 1) * 4;

    auto load_q = [&]() {
        const __half* src = g_Qh + (size_t)(tok0 + srow) * MEMD + h * HDIM + sq2 * 8;
        uint32_t dst = sQ + srow * AT_ROW + sq2 * 16;
        #pragma unroll
        for (int u = 0; u < 4; u++) CP_ASYNC16(dst + u * 16, src + u * 8);
    };
    auto load_kv = [&](int c) {
        const int b = c & 1;
        const __half* ks = g_KVh + (size_t)(c * 128 + srow) * 512 + h * HDIM + sq2 * 8;
        const __half* vs = ks + 256;
        uint32_t kd = sK[b] + srow * AT_ROW + sq2 * 16;
        uint32_t vd = sV[b] + srow * AT_ROW + sq2 * 16;
        #pragma unroll
        for (int u = 0; u < 4; u++) { CP_ASYNC16(kd + u * 16, ks + u * 8); CP_ASYNC16(vd + u * 16, vs + u * 8); }
    };

    load_q(); load_kv(0); CP_COMMIT();
    load_kv(1); CP_COMMIT();
    CP_WAIT1();
    __syncthreads();

    const int grp = lane >> 3;
    const int r8  = lane & 7;
    const int wbase = w * 16;
    const uint32_t a_addr = (uint32_t)(wbase + (grp & 1) * 8 + r8) * AT_ROW + (grp >> 1) * 16;
    const uint32_t b_addr = (uint32_t)((grp >> 1) * 8 + r8) * AT_ROW + (grp & 1) * 16;
    const uint32_t v_addr = (uint32_t)(r8 + 8 * (grp & 1)) * AT_ROW + (lane >> 4) * 16;

    uint32_t qf[4][4];
    #pragma unroll
    for (int kk = 0; kk < 4; kk++)
        LDSM_X4(qf[kk][0], qf[kk][1], qf[kk][2], qf[kk][3],
                sQ + a_addr + kk * 32);

    float ctx[8][4];
    #pragma unroll
    for (int i = 0; i < 8; i++)
        #pragma unroll
        for (int q = 0; q < 4; q++) ctx[i][q] = 0.f;
    float lrow = 0.f, lrow8 = 0.f;

    for (int c = 0; c < 4; c++) {
        const int b = c & 1;

        float sacc[16][4];
        #pragma unroll
        for (int i = 0; i < 16; i++)
            #pragma unroll
            for (int q = 0; q < 4; q++) sacc[i][q] = 0.f;

        #pragma unroll
        for (int nt2 = 0; nt2 < 8; nt2++) {
            #pragma unroll
            for (int kk = 0; kk < 4; kk++) {
                uint32_t kb[4];
                LDSM_X4(kb[0], kb[1], kb[2], kb[3],
                        sK[b] + b_addr + (uint32_t)nt2 * (16 * AT_ROW) + kk * 32);
                MMA16816(sacc[2 * nt2],     qf[kk], kb[0], kb[1]);
                MMA16816(sacc[2 * nt2 + 1], qf[kk], kb[2], kb[3]);
            }
        }

        uint32_t pf[8][4];
        #pragma unroll
        for (int kf = 0; kf < 8; kf++) {
            float e00 = __expf(sacc[2 * kf][0]);
            float e01 = __expf(sacc[2 * kf][1]);
            float e02 = __expf(sacc[2 * kf][2]);
            float e03 = __expf(sacc[2 * kf][3]);
            float e10 = __expf(sacc[2 * kf + 1][0]);
            float e11 = __expf(sacc[2 * kf + 1][1]);
            float e12 = __expf(sacc[2 * kf + 1][2]);
            float e13 = __expf(sacc[2 * kf + 1][3]);
            lrow  += e00 + e01 + e10 + e11;
            lrow8 += e02 + e03 + e12 + e13;
            __half2 h0 = __floats2half2_rn(e00, e01);
            __half2 h1 = __floats2half2_rn(e02, e03);
            __half2 h2 = __floats2half2_rn(e10, e11);
            __half2 h3 = __floats2half2_rn(e12, e13);
            pf[kf][0] = *(uint32_t*)&h0;
            pf[kf][1] = *(uint32_t*)&h1;
            pf[kf][2] = *(uint32_t*)&h2;
            pf[kf][3] = *(uint32_t*)&h3;
        }

        #pragma unroll
        for (int dt2 = 0; dt2 < 4; dt2++) {
            #pragma unroll
            for (int kf = 0; kf < 8; kf++) {
                uint32_t vb[4];
                LDSM_X4T(vb[0], vb[1], vb[2], vb[3],
                         sV[b] + v_addr + (uint32_t)kf * (16 * AT_ROW) + dt2 * 32);
                MMA16816(ctx[2 * dt2],     pf[kf], vb[0], vb[1]);
                MMA16816(ctx[2 * dt2 + 1], pf[kf], vb[2], vb[3]);
            }
        }

        __syncthreads();
        if (c + 2 < 4) { load_kv(c + 2); CP_COMMIT(); }
        if (c + 1 < 4) {
            if (c + 2 < 4) CP_WAIT1(); else CP_WAIT0();
            __syncthreads();
        }
    }

    lrow  += __shfl_xor_sync(0xffffffffu, lrow, 1);
    lrow  += __shfl_xor_sync(0xffffffffu, lrow, 2);
    lrow8 += __shfl_xor_sync(0xffffffffu, lrow8, 1);
    lrow8 += __shfl_xor_sync(0xffffffffu, lrow8, 2);
    const float inv  = 1.f / lrow;
    const float inv8 = 1.f / lrow8;

    const int rowA = tok0 + wbase + (lane >> 2);
    const int colb = h * HDIM + 2 * (lane & 3);
    #pragma unroll
    for (int dt = 0; dt < 8; dt++) {
        int gn = colb + dt * 8;
        *(__half2*)(g_CTX + (size_t)rowA * MEMD + gn) =
            __floats2half2_rn(ctx[dt][0] * inv, ctx[dt][1] * inv);
        *(__half2*)(g_CTX + (size_t)(rowA + 8) * MEMD + gn) =
            __floats2half2_rn(ctx[dt][2] * inv8, ctx[dt][3] * inv8);
    }
}

// ---------------------------------------------------------------------------
// top-k by rank counting (exact set == lax.top_k)
// ---------------------------------------------------------------------------
__global__ void mr_topk_kernel(const float* __restrict__ scores) {
    __shared__ float s[NMEM];
    for (int i = threadIdx.x; i < NMEM; i += 512) s[i] = scores[i];
    __syncthreads();
    int i = blockIdx.x * 512 + threadIdx.x;
    float si = s[i];
    int cnt = 0;
    #pragma unroll 8
    for (int j = 0; j < NMEM; j++) {
        float sj = s[j];
        cnt += (sj > si) || (sj == si && j < i);
    }
    if (cnt < TOPK) g_idx[cnt] = i;
}

// Wq_comb = (wq @ qp_w)/8 -> fp16 ;  bq_comb = (wq@qp_b + bq)/8
__global__ void mr_wqcomb_kernel(const float* __restrict__ in_proj_w,
                                 const float* __restrict__ qp_w,
                                 const float* __restrict__ qp_b,
                                 const float* __restrict__ in_proj_b) {
    int m = blockIdx.x;
    __shared__ float wrow[MEMD];
    for (int j = threadIdx.x; j < MEMD; j += 256)
        wrow[j] = in_proj_w[(size_t)m * MEMD + j];
    __syncthreads();
    #pragma unroll
    for (int cc = 0; cc < HID / 256; cc++) {
        int hcol = threadIdx.x + 256 * cc;
        float acc = 0.f;
        #pragma unroll 8
        for (int j = 0; j < MEMD; j++)
            acc += wrow[j] * qp_w[(size_t)j * HID + hcol];
        g_WQ[(size_t)m * HID + hcol] = __float2half_rn(0.125f * acc);
    }
    if (threadIdx.x == 0) {
        float acc = in_proj_b[m];
        for (int j = 0; j < MEMD; j++) acc += wrow[j] * qp_b[j];
        g_BQ[m] = 0.125f * acc;
    }
}

__device__ __forceinline__ void block_reduce2(float& a, float& b) {
    #pragma unroll
    for (int o = 16; o > 0; o >>= 1) {
        a += __shfl_xor_sync(0xffffffffu, a, o);
        b += __shfl_xor_sync(0xffffffffu, b, o);
    }
    __shared__ float sa[8], sb2[8];
    int w = threadIdx.x >> 5;
    if ((threadIdx.x & 31) == 0) { sa[w] = a; sb2[w] = b; }
    __syncthreads();
    a = 0.f; b = 0.f;
    #pragma unroll
    for (int i = 0; i < 8; i++) { a += sa[i]; b += sb2[i]; }
}

__global__ void mr_gather_ln_kernel(const float* __restrict__ mk,
                                    const float* __restrict__ g,
                                    const float* __restrict__ b) {
    int r = blockIdx.x;
    int t = threadIdx.x;
    float v = mk[(size_t)g_idx[r] * MEMD + t];
    float s = v, ss = v * v;
    block_reduce2(s, ss);
    float mu  = s * (1.f / MEMD);
    float var = ss * (1.f / MEMD) - mu * mu;
    g_MEM[(size_t)r * MEMD + t] = (v - mu) * rsqrtf(var + 1e-5f) * g[t] + b[t];
}

// fp32 -> fp16, vectorized
__global__ void mr_cvt_kernel(const float* __restrict__ s,
                              __half* __restrict__ d, int n4) {
    int i = blockIdx.x * 256 + threadIdx.x;
    if (i >= n4) return;
    float4 v = ((const float4*)s)[i];
    ((__half2*)d)[2 * i]     = __floats2half2_rn(v.x, v.y);
    ((__half2*)d)[2 * i + 1] = __floats2half2_rn(v.z, v.w);
}

// X -> CAT left 1024 columns (fp16)
__global__ void mr_copyx_cvt_kernel(const float* __restrict__ X) {
    size_t i4  = (size_t)blockIdx.x * 256 + threadIdx.x;
    size_t row = i4 >> 8;
    size_t c4  = i4 & 255;
    float4 v = ((const float4*)X)[i4];
    size_t o = row * CATD + c4 * 4;
    *(__half2*)(g_CAT + o)     = __floats2half2_rn(v.x, v.y);
    *(__half2*)(g_CAT + o + 2) = __floats2half2_rn(v.z, v.w);
}

// ---------------------------------------------------------------------------
// FFMA2 SGEMM (K/V projection): C(half) = A@B^T + bias
// ---------------------------------------------------------------------------
__global__ void __launch_bounds__(256) mr_sgemm_kernel(
    const float* __restrict__ A, const float* __restrict__ B,
    const float* __restrict__ bias, __half* __restrict__ C,
    int K, int ldc)
{
    __shared__ float2 As[8][128];
    __shared__ float  Bs[8][128];

    const int tid  = threadIdx.x;
    const int row0 = blockIdx.y * 128;
    const int col0 = blockIdx.x * 128;
    const int lr   = tid >> 1;
    const int lh   = tid & 1;
    const float* Ag = A + (size_t)(row0 + lr) * K + lh * 4;
    const float* Bg = B + (size_t)(col0 + lr) * K + lh * 4;
    const int tx = tid & 15;
    const int ty = tid >> 4;

    unsigned long long acc[8][4];
    #pragma unroll
    for (int i = 0; i < 8; i++)
        #pragma unroll
        for (int j = 0; j < 4; j++) acc[i][j] = 0ULL;

    for (int kt = 0; kt < K; kt += 8) {
        float4 av = *(const float4*)(Ag + kt);
        float4 bv = *(const float4*)(Bg + kt);
        __syncthreads();
        As[lh * 4 + 0][lr] = make_float2(av.x, av.x);
        As[lh * 4 + 1][lr] = make_float2(av.y, av.y);
        As[lh * 4 + 2][lr] = make_float2(av.z, av.z);
        As[lh * 4 + 3][lr] = make_float2(av.w, av.w);
        Bs[lh * 4 + 0][lr] = bv.x;
        Bs[lh * 4 + 1][lr] = bv.y;
        Bs[lh * 4 + 2][lr] = bv.z;
        Bs[lh * 4 + 3][lr] = bv.w;
        __syncthreads();
        #pragma unroll
        for (int kk = 0; kk < 8; kk++) {
            unsigned long long a2[8], b2[4];
            const unsigned long long* ap = (const unsigned long long*)&As[kk][ty * 8];
            #pragma unroll
            for (int i = 0; i < 8; i++) a2[i] = ap[i];
            const unsigned long long* bp = (const unsigned long long*)&Bs[kk][tx * 8];
            #pragma unroll
            for (int j = 0; j < 4; j++) b2[j] = bp[j];
            #pragma unroll
            for (int i = 0; i < 8; i++)
                #pragma unroll
                for (int j = 0; j < 4; j++)
                    FMA2(acc[i][j], a2[i], b2[j]);
        }
    }

    #pragma unroll
    for (int i = 0; i < 8; i++) {
        __half* crow = C + (size_t)(row0 + ty * 8 + i) * ldc + col0 + tx * 8;
        #pragma unroll
        for (int j = 0; j < 4; j++) {
            float x, y;
            UNPACK2(x, y, acc[i][j]);
            float2 bb = *(const float2*)(bias + col0 + tx * 8 + 2 * j);
            *(__half2*)(crow + 2 * j) = __floats2half2_rn(x + bb.x, y + bb.y);
        }
    }
}

// h = gelu_exact(LN(h_pre)) -> fp16  (h_pre fp16 in, stats fp32)
__global__ void mr_ln_gelu_kernel(const float* __restrict__ g,
                                  const float* __restrict__ b) {
    const size_t row = blockIdx.x;
    const __half2* p = (const __half2*)(g_Hpre + row * H2D);
    float x[8];
    #pragma unroll
    for (int i = 0; i < 4; i++) {
        float2 v = __half22float2(p[threadIdx.x + 256 * i]);
        x[2 * i] = v.x; x[2 * i + 1] = v.y;
    }
    float s = 0.f, ss = 0.f;
    #pragma unroll
    for (int i = 0; i < 8; i++) { s += x[i]; ss += x[i] * x[i]; }
    block_reduce2(s, ss);
    float mu  = s * (1.f / H2D);
    float var = ss * (1.f / H2D) - mu * mu;
    float rs  = rsqrtf(var + 1e-5f);
    #pragma unroll
    for (int i = 0; i < 4; i++) {
        int col = (threadIdx.x + 256 * i) * 2;
        float t0 = (x[2 * i]     - mu) * rs * g[col]     + b[col];
        float t1 = (x[2 * i + 1] - mu) * rs * g[col + 1] + b[col + 1];
        float g0 = 0.5f * t0 * (1.f + erff(t0 * 0.70710678118654752f));
        float g1 = 0.5f * t1 * (1.f + erff(t1 * 0.70710678118654752f));
        *(__half2*)(g_Hh + row * H2D + col) = __floats2half2_rn(g0, g1);
    }
}

// out = LN(X + gate*integ)   (gate/integ fp16, X fp32)
__global__ void mr_final_kernel(const float* __restrict__ X,
                                const float* __restrict__ g,
                                const float* __restrict__ b,
                                float* __restrict__ out) {
    const size_t row = blockIdx.x;
    const float*  xp = X + row * HID;
    const __half2* gp = (const __half2*)(g_GATEh + row * HID);
    const __half2* ip = (const __half2*)(g_INTh + row * HID);
    float v[4];
    float s = 0.f, ss = 0.f;
    #pragma unroll
    for (int i = 0; i < 2; i++) {
        int c2 = threadIdx.x + 256 * i;
        float2 gg = __half22float2(gp[c2]);
        float2 ii = __half22float2(ip[c2]);
        float2 xx = *(const float2*)(xp + 2 * c2);
        v[2 * i]     = xx.x + gg.x * ii.x;
        v[2 * i + 1] = xx.y + gg.y * ii.y;
        s += v[2 * i] + v[2 * i + 1];
        ss += v[2 * i] * v[2 * i] + v[2 * i + 1] * v[2 * i + 1];
    }
    block_reduce2(s, ss);
    float mu  = s * (1.f / HID);
    float var = ss * (1.f / HID) - mu * mu;
    float rs  = rsqrtf(var + 1e-5f);
    #pragma unroll
    for (int i = 0; i < 2; i++) {
        int col = (threadIdx.x + 256 * i) * 2;
        out[row * HID + col]     = (v[2 * i]     - mu) * rs * g[col]     + b[col];
        out[row * HID + col + 1] = (v[2 * i + 1] - mu) * rs * g[col + 1] + b[col + 1];
    }
}

// ---------------------------------------------------------------------------
extern "C" void kernel_launch(void* const* d_in, const int* in_sizes, int n_in,
                              void* d_out, int out_size) {
    const float* X         = (const float*)d_in[0];
    const float* mem_keys  = (const float*)d_in[1];
    const float* sel       = (const float*)d_in[2];
    const float* qp_w      = (const float*)d_in[3];
    const float* qp_b      = (const float*)d_in[4];
    const float* in_proj_w = (const float*)d_in[5];
    const float* in_proj_b = (const float*)d_in[6];
    const float* out_w     = (const float*)d_in[7];
    const float* out_b     = (const float*)d_in[8];
    const float* gate_w    = (const float*)d_in[9];
    const float* gate_b    = (const float*)d_in[10];
    const float* int_w1    = (const float*)d_in[11];
    const float* int_b1    = (const float*)d_in[12];
    const float* int_ln_g  = (const float*)d_in[13];
    const float* int_ln_b  = (const float*)d_in[14];
    const float* int_w2    = (const float*)d_in[15];
    const float* int_b2    = (const float*)d_in[16];
    const float* ln1_g     = (const float*)d_in[17];
    const float* ln1_b     = (const float*)d_in[18];
    const float* ln2_g     = (const float*)d_in[19];
    const float* ln2_b     = (const float*)d_in[20];
    float* out = (float*)d_out;

    static int smem_set = 0;
    if (!smem_set) {
        cudaFuncSetAttribute(mr_mma_gemm,
                             cudaFuncAttributeMaxDynamicSharedMemorySize, GSMEM);
        cudaFuncSetAttribute(mr_fattn_kernel,
                             cudaFuncAttributeMaxDynamicSharedMemorySize, AT_SMEM);
        smem_set = 1;
    }

    float *pMEM, *pBQ, *pB3;
    __half *pKVh, *pQh, *pCAT, *pCTX, *pINTh, *pWQ, *pGW1, *pW2, *pOW, *pHh;
    cudaGetSymbolAddress((void**)&pMEM, g_MEM);
    cudaGetSymbolAddress((void**)&pBQ,  g_BQ);
    cudaGetSymbolAddress((void**)&pB3,  g_B3);
    cudaGetSymbolAddress((void**)&pKVh, g_KVh);
    cudaGetSymbolAddress((void**)&pQh,  g_Qh);
    cudaGetSymbolAddress((void**)&pCAT, g_CAT);
    cudaGetSymbolAddress((void**)&pCTX, g_CTX);
    cudaGetSymbolAddress((void**)&pINTh, g_INTh);
    cudaGetSymbolAddress((void**)&pWQ,  g_WQ);
    cudaGetSymbolAddress((void**)&pGW1, g_GW1);
    cudaGetSymbolAddress((void**)&pW2,  g_W2);
    cudaGetSymbolAddress((void**)&pOW,  g_OW);
    cudaGetSymbolAddress((void**)&pHh,  g_Hh);

    auto mmagemm = [&](const __half* A, int lda, const __half* B, int ldb,
                       const float* bias, __half* Ch,
                       int ldc, int M, int N, int K, int act) {
        dim3 gd(N / 128, M / 128);
        mr_mma_gemm<<<gd, 256, GSMEM>>>(A, lda, B, ldb, bias, Ch, ldc, K, act);
    };

    // selection + memory prep
    mr_topk_kernel<<<8, 512>>>(sel);
    mr_wqcomb_kernel<<<256, 256>>>(in_proj_w, qp_w, qp_b, in_proj_b);
    mr_gather_ln_kernel<<<TOPK, 256>>>(mem_keys, ln1_g, ln1_b);

    // combined bias [gate_b ; int_b1]
    cudaMemcpyAsync(pB3, gate_b, HID * sizeof(float), cudaMemcpyDeviceToDevice);
    cudaMemcpyAsync(pB3 + HID, int_b1, H2D * sizeof(float), cudaMemcpyDeviceToDevice);

    // weight converts
    mr_cvt_kernel<<<(HID * CATD / 4 + 255) / 256, 256>>>(gate_w, pGW1, HID * CATD / 4);
    mr_cvt_kernel<<<(H2D * CATD / 4 + 255) / 256, 256>>>(int_w1,
        pGW1 + (size_t)HID * CATD, H2D * CATD / 4);
    mr_cvt_kernel<<<(HID * H2D / 4 + 255) / 256, 256>>>(int_w2, pW2, HID * H2D / 4);
    mr_cvt_kernel<<<(MEMD * MEMD / 4 + 255) / 256, 256>>>(out_w, pOW, MEMD * MEMD / 4);

    // K|V projection (fp16 out): KV[512,512] = MEM @ [wk;wv]^T + [bk;bv]
    {
        dim3 gd(4, 4);
        mr_sgemm_kernel<<<gd, 256>>>(pMEM, in_proj_w + MEMD * MEMD,
                                     in_proj_b + MEMD, pKVh, MEMD, 512);
    }

    // X -> CAT (left 1024 cols, fp16)
    mr_copyx_cvt_kernel<<<(size_t)BS_TOK * HID / 4 / 256, 256>>>(X);

    // q = X @ Wq_comb^T + bq  (1/8 folded)  -> fp16
    mmagemm(pCAT, CATD, pWQ, HID, pBQ, pQh, MEMD, BS_TOK, MEMD, HID, 2);

    // flash attention -> CTX (fp16)
    mr_fattn_kernel<<<dim3(BS_TOK / 128, NHEAD), 256, AT_SMEM>>>();

    // attn_out = ctx @ out_w^T + out_b  -> CAT right 256 cols (fp16)
    mmagemm(pCTX, MEMD, pOW, MEMD, out_b, pCAT + HID, CATD, BS_TOK, MEMD, MEMD, 2);

    // fused: gate = sigmoid(cat@gate_w^T+gate_b) -> fp16,
    //        h_pre = cat@int_w1^T+int_b1 -> fp16
    mmagemm(pCAT, CATD, pGW1, CATD, pB3, nullptr, 0, BS_TOK, 3072, CATD, 3);

    mr_ln_gelu_kernel<<<BS_TOK, 256>>>(int_ln_g, int_ln_b);

    // integrated = h@int_w2^T + int_b2 -> fp16
    mmagemm(pHh, H2D, pW2, H2D, int_b2, pINTh, HID, BS_TOK, HID, H2D, 2);

    // out = LN(X + gate*integrated)
    mr_final_kernel<<<BS_TOK, 256>>>(X, ln2_g, ln2_b, out);
}